// round 1
// baseline (speedup 1.0000x reference)
#include <cuda_runtime.h>
#include <cstdint>

// Problem constants
constexpr int BATCH = 2, SEQ = 2048, DMODEL = 4096;
constexpr int NH = 32, NKV = 8, HD = 128;
constexpr int MROWS = BATCH * SEQ;              // 4096
constexpr float ATT_SCALE = 0.08838834764831845f; // 128^-0.5

// Scratch (static device globals -- allocation-free per harness rules)
__device__ float g_q [(size_t)BATCH * NH  * SEQ * HD];  // [b,h,s,d] rope'd, *scale, tf32-rounded
__device__ float g_k [(size_t)BATCH * NKV * SEQ * HD];  // [b,h,s,d] rope'd, tf32-rounded
__device__ float g_vt[(size_t)BATCH * NKV * HD * SEQ];  // [b,h,d,s] transposed, tf32-rounded
__device__ float g_ao[(size_t)MROWS * DMODEL];          // attention output, token-major

__device__ __forceinline__ float tf32r(float x) {
    uint32_t u;
    asm("cvt.rna.tf32.f32 %0, %1;" : "=r"(u) : "f"(x));
    return __uint_as_float(u);
}

__device__ __forceinline__ void mma8(float* c, const uint32_t* a, const uint32_t* b) {
    asm volatile(
        "mma.sync.aligned.m16n8k8.row.col.f32.tf32.tf32.f32 "
        "{%0,%1,%2,%3}, {%4,%5,%6,%7}, {%8,%9}, {%0,%1,%2,%3};"
        : "+f"(c[0]), "+f"(c[1]), "+f"(c[2]), "+f"(c[3])
        : "r"(a[0]), "r"(a[1]), "r"(a[2]), "r"(a[3]), "r"(b[0]), "r"(b[1]));
}

// ---------------------------------------------------------------------------
// GEMM: C[M=4096, N] = A[M,4096] @ W^T (W rows are output features, K-major)
// MODE 0: QKV projection; N-tile == one head (128 cols). Epilogue: RoPE + scatter.
// MODE 1: output projection; plain epilogue to Cout.
// Tiles: BM=128, BN=128, BK=32. 256 threads, 8 warps (4m x 2n), warp = 32x64.
// ---------------------------------------------------------------------------
template <int MODE>
__global__ void __launch_bounds__(256, 1)
gemm_tf32(const float* __restrict__ A,
          const float* __restrict__ W0,
          const float* __restrict__ W1,
          const float* __restrict__ W2,
          const float* __restrict__ cosp,
          const float* __restrict__ sinp,
          float* __restrict__ Cout)
{
    constexpr int BM = 128, BK = 32, ASTR = BK + 4; // pad -> conflict-free frags
    extern __shared__ float smf[];
    float* As = smf;                     // 2 buffers * 128*36
    float* Bs = smf + 2 * BM * ASTR;     // 2 buffers * 128*36

    const int tid = threadIdx.x;
    const int bn = blockIdx.x, bm = blockIdx.y;
    const int m0 = bm * BM;

    const float* Ap = (MODE == 1) ? g_ao : A;

    const float* W;
    int nbase, btype = 0, hidx = 0;
    if (MODE == 0) {
        if (bn < 32)      { W = W0; nbase = bn * 128;        btype = 0; hidx = bn; }
        else if (bn < 40) { W = W1; nbase = (bn - 32) * 128; btype = 1; hidx = bn - 32; }
        else              { W = W2; nbase = (bn - 40) * 128; btype = 2; hidx = bn - 40; }
    } else {
        W = W0; nbase = bn * 128;
    }

    float4 ra[4], rb[4];
    auto loadg = [&](int kt) {
        const int k0 = kt * BK;
#pragma unroll
        for (int i = 0; i < 4; i++) {
            int f = tid + i * 256;
            int row = f >> 3, c4 = (f & 7) * 4;
            ra[i] = *(const float4*)(Ap + (size_t)(m0 + row) * 4096 + k0 + c4);
            rb[i] = *(const float4*)(W  + (size_t)(nbase + row) * 4096 + k0 + c4);
        }
    };
    auto stores = [&](int buf) {
        float* Ab = As + buf * BM * ASTR;
        float* Bb = Bs + buf * BM * ASTR;
#pragma unroll
        for (int i = 0; i < 4; i++) {
            int f = tid + i * 256;
            int row = f >> 3, c4 = (f & 7) * 4;
            float4 va = ra[i];
            va.x = tf32r(va.x); va.y = tf32r(va.y); va.z = tf32r(va.z); va.w = tf32r(va.w);
            float4 vb = rb[i];
            vb.x = tf32r(vb.x); vb.y = tf32r(vb.y); vb.z = tf32r(vb.z); vb.w = tf32r(vb.w);
            *(float4*)(Ab + row * ASTR + c4) = va;
            *(float4*)(Bb + row * ASTR + c4) = vb;
        }
    };

    const int lane = tid & 31, wid = tid >> 5;
    const int gi = lane >> 2, ti = lane & 3;
    const int wm = wid >> 1, wn = wid & 1;

    float acc[2][8][4];
#pragma unroll
    for (int a = 0; a < 2; a++)
#pragma unroll
        for (int b = 0; b < 8; b++)
#pragma unroll
            for (int c = 0; c < 4; c++) acc[a][b][c] = 0.f;

    const int NK = 4096 / BK; // 128
    loadg(0);
    stores(0);
    for (int kt = 0; kt < NK; kt++) {
        if (kt + 1 < NK) loadg(kt + 1);
        __syncthreads();
        if (kt + 1 < NK) stores((kt + 1) & 1);
        const float* Ab = As + (kt & 1) * BM * ASTR;
        const float* Bb = Bs + (kt & 1) * BM * ASTR;
#pragma unroll
        for (int kk = 0; kk < BK; kk += 8) {
            uint32_t af[2][4];
#pragma unroll
            for (int mt = 0; mt < 2; mt++) {
                int r = wm * 32 + mt * 16 + gi;
                af[mt][0] = __float_as_uint(Ab[r * ASTR + kk + ti]);
                af[mt][1] = __float_as_uint(Ab[(r + 8) * ASTR + kk + ti]);
                af[mt][2] = __float_as_uint(Ab[r * ASTR + kk + ti + 4]);
                af[mt][3] = __float_as_uint(Ab[(r + 8) * ASTR + kk + ti + 4]);
            }
#pragma unroll
            for (int nt = 0; nt < 8; nt++) {
                int n = wn * 64 + nt * 8 + gi;
                uint32_t bf[2];
                bf[0] = __float_as_uint(Bb[n * ASTR + kk + ti]);
                bf[1] = __float_as_uint(Bb[n * ASTR + kk + ti + 4]);
                mma8(acc[0][nt], af[0], bf);
                mma8(acc[1][nt], af[1], bf);
            }
        }
    }
    __syncthreads(); // done reading smem tiles; safe to reuse

    if (MODE == 1) {
#pragma unroll
        for (int mt = 0; mt < 2; mt++)
#pragma unroll
            for (int nt = 0; nt < 8; nt++) {
                int r = m0 + wm * 32 + mt * 16 + gi;
                int c = bn * 128 + wn * 64 + nt * 8 + 2 * ti;
                *(float2*)(Cout + (size_t)r * 4096 + c) =
                    make_float2(acc[mt][nt][0], acc[mt][nt][1]);
                *(float2*)(Cout + (size_t)(r + 8) * 4096 + c) =
                    make_float2(acc[mt][nt][2], acc[mt][nt][3]);
            }
        return;
    }

    // MODE 0 epilogue: C tile -> smem, then RoPE / scatter
    float* Csh = smf; // 128 x 132 floats (fits in the 73728B tile region)
#pragma unroll
    for (int mt = 0; mt < 2; mt++)
#pragma unroll
        for (int nt = 0; nt < 8; nt++) {
            int r = wm * 32 + mt * 16 + gi, c = wn * 64 + nt * 8 + 2 * ti;
            Csh[r * 132 + c]           = acc[mt][nt][0];
            Csh[r * 132 + c + 1]       = acc[mt][nt][1];
            Csh[(r + 8) * 132 + c]     = acc[mt][nt][2];
            Csh[(r + 8) * 132 + c + 1] = acc[mt][nt][3];
        }
    __syncthreads();

    const int bb = m0 >> 11; // whole tile within one batch (2048 % 128 == 0)
    if (btype < 2) {
        // Q or K: apply RoPE; fold ATT_SCALE into Q
#pragma unroll 4
        for (int i = 0; i < 64; i++) {
            int f = tid + i * 256;
            int r = f >> 7, d = f & 127;
            int m = m0 + r, s = m & 2047;
            float val = Csh[r * 132 + d];
            float oth = Csh[r * 132 + ((d + 64) & 127)];
            float rot = (d < 64) ? -oth : oth;
            float cs = cosp[(size_t)m * HD + d];
            float sn = sinp[(size_t)m * HD + d];
            float ov = val * cs + rot * sn;
            if (btype == 0)
                g_q[(((size_t)bb * NH + hidx) * SEQ + s) * HD + d] = tf32r(ov * ATT_SCALE);
            else
                g_k[(((size_t)bb * NKV + hidx) * SEQ + s) * HD + d] = tf32r(ov);
        }
    } else {
        // V: write transposed [b,h,d,s]
#pragma unroll 4
        for (int i = 0; i < 64; i++) {
            int f = tid + i * 256;
            int d = f >> 7, sl = f & 127;
            int m = m0 + sl, s = m & 2047;
            g_vt[(((size_t)bb * NKV + hidx) * HD + d) * SEQ + s] = tf32r(Csh[sl * 132 + d]);
        }
    }
}

// ---------------------------------------------------------------------------
// Flash attention: per (q-tile of 128, head, batch). 256 threads = 8 warps,
// warp owns 16 q-rows. kv tile = 64. Online softmax in fp32, MMAs in tf32.
// ---------------------------------------------------------------------------
__global__ void __launch_bounds__(256, 1) attn_kernel()
{
    extern __shared__ float smf[];
    float* Qs  = smf;                  // 128 x 132
    float* Ks  = Qs + 128 * 132;       // 64  x 132
    float* Vts = Ks + 64 * 132;        // 128 x 68   (V^T: [d][s])
    float* Ps  = Vts + 128 * 68;       // 128 x 68   (probs)

    const int tid = threadIdx.x, lane = tid & 31, wid = tid >> 5;
    const int gi = lane >> 2, ti = lane & 3;
    const int qt = blockIdx.x, h = blockIdx.y, b = blockIdx.z;
    const int q0 = qt * 128, hk = h >> 2; // GROUPS = 4

    const float* Qg = g_q + (((size_t)b * NH + h) * SEQ + q0) * HD;
    const float* Kg = g_k + ((size_t)b * NKV + hk) * SEQ * HD;
    const float* Vg = g_vt + ((size_t)b * NKV + hk) * HD * SEQ;

#pragma unroll
    for (int i = 0; i < 16; i++) {
        int f = tid + i * 256;
        int r = f >> 5, c = (f & 31) * 4;
        *(float4*)(Qs + r * 132 + c) = *(const float4*)(Qg + (size_t)r * HD + c);
    }

    float o[16][4];
#pragma unroll
    for (int a = 0; a < 16; a++)
#pragma unroll
        for (int c = 0; c < 4; c++) o[a][c] = 0.f;
    float mrow[2] = {-1e30f, -1e30f};
    float lrow[2] = {0.f, 0.f};

    const int ktmax = 2 * qt + 1; // causal
    for (int kt = 0; kt <= ktmax; kt++) {
        __syncthreads(); // protect K/V smem vs previous iteration readers
#pragma unroll
        for (int i = 0; i < 8; i++) {
            int f = tid + i * 256;
            int r = f >> 5, c = (f & 31) * 4;
            *(float4*)(Ks + r * 132 + c) =
                *(const float4*)(Kg + (size_t)(kt * 64 + r) * HD + c);
        }
#pragma unroll
        for (int i = 0; i < 8; i++) {
            int f = tid + i * 256;
            int d = f >> 4, c = (f & 15) * 4;
            *(float4*)(Vts + d * 68 + c) =
                *(const float4*)(Vg + (size_t)d * SEQ + kt * 64 + c);
        }
        __syncthreads();

        // S = Q @ K^T (scale already folded into Q)
        float sacc[8][4];
#pragma unroll
        for (int a = 0; a < 8; a++)
#pragma unroll
            for (int c = 0; c < 4; c++) sacc[a][c] = 0.f;
#pragma unroll
        for (int kk = 0; kk < HD; kk += 8) {
            uint32_t af[4];
            int r = wid * 16 + gi;
            af[0] = __float_as_uint(Qs[r * 132 + kk + ti]);
            af[1] = __float_as_uint(Qs[(r + 8) * 132 + kk + ti]);
            af[2] = __float_as_uint(Qs[r * 132 + kk + ti + 4]);
            af[3] = __float_as_uint(Qs[(r + 8) * 132 + kk + ti + 4]);
#pragma unroll
            for (int nt = 0; nt < 8; nt++) {
                int n = nt * 8 + gi;
                uint32_t bf[2];
                bf[0] = __float_as_uint(Ks[n * 132 + kk + ti]);
                bf[1] = __float_as_uint(Ks[n * 132 + kk + ti + 4]);
                mma8(sacc[nt], af, bf);
            }
        }

        // causal mask (only tiles overlapping the diagonal need it)
        if (kt * 64 + 63 > q0 + wid * 16) {
#pragma unroll
            for (int nt = 0; nt < 8; nt++)
#pragma unroll
                for (int j = 0; j < 4; j++) {
                    int col = kt * 64 + nt * 8 + 2 * ti + (j & 1);
                    int row = q0 + wid * 16 + gi + (j >> 1) * 8;
                    if (col > row) sacc[nt][j] = -1e30f;
                }
        }

        // online softmax (two row-halves per thread: gi and gi+8)
#pragma unroll
        for (int j = 0; j < 2; j++) {
            float mx = -1e30f;
#pragma unroll
            for (int nt = 0; nt < 8; nt++)
                mx = fmaxf(mx, fmaxf(sacc[nt][2 * j], sacc[nt][2 * j + 1]));
            mx = fmaxf(mx, __shfl_xor_sync(0xffffffffu, mx, 1));
            mx = fmaxf(mx, __shfl_xor_sync(0xffffffffu, mx, 2));
            float newm = fmaxf(mrow[j], mx);
            float alpha = __expf(mrow[j] - newm);
            mrow[j] = newm;
            float rs = 0.f;
#pragma unroll
            for (int nt = 0; nt < 8; nt++) {
                float p0 = __expf(sacc[nt][2 * j] - newm);
                float p1 = __expf(sacc[nt][2 * j + 1] - newm);
                sacc[nt][2 * j] = p0; sacc[nt][2 * j + 1] = p1;
                rs += p0 + p1;
            }
            rs += __shfl_xor_sync(0xffffffffu, rs, 1);
            rs += __shfl_xor_sync(0xffffffffu, rs, 2);
            lrow[j] = lrow[j] * alpha + rs;
#pragma unroll
            for (int nt = 0; nt < 16; nt++) {
                o[nt][2 * j] *= alpha; o[nt][2 * j + 1] *= alpha;
            }
            int r = wid * 16 + gi + j * 8;
#pragma unroll
            for (int nt = 0; nt < 8; nt++) {
                Ps[r * 68 + nt * 8 + 2 * ti]     = tf32r(sacc[nt][2 * j]);
                Ps[r * 68 + nt * 8 + 2 * ti + 1] = tf32r(sacc[nt][2 * j + 1]);
            }
        }
        __syncwarp(); // P produced/consumed within the same warp

        // O += P @ V
#pragma unroll
        for (int kk = 0; kk < 64; kk += 8) {
            uint32_t af[4];
            int r = wid * 16 + gi;
            af[0] = __float_as_uint(Ps[r * 68 + kk + ti]);
            af[1] = __float_as_uint(Ps[(r + 8) * 68 + kk + ti]);
            af[2] = __float_as_uint(Ps[r * 68 + kk + ti + 4]);
            af[3] = __float_as_uint(Ps[(r + 8) * 68 + kk + ti + 4]);
#pragma unroll
            for (int nt = 0; nt < 16; nt++) {
                int n = nt * 8 + gi;
                uint32_t bf[2];
                bf[0] = __float_as_uint(Vts[n * 68 + kk + ti]);
                bf[1] = __float_as_uint(Vts[n * 68 + kk + ti + 4]);
                mma8(o[nt], af, bf);
            }
        }
    }

    __syncthreads(); // all warps done reading Qs before reuse as staging
    const float inv0 = 1.f / lrow[0], inv1 = 1.f / lrow[1];
    {
        int r = wid * 16 + gi;
#pragma unroll
        for (int nt = 0; nt < 16; nt++) {
            int c = nt * 8 + 2 * ti;
            Qs[r * 132 + c]           = o[nt][0] * inv0;
            Qs[r * 132 + c + 1]       = o[nt][1] * inv0;
            Qs[(r + 8) * 132 + c]     = o[nt][2] * inv1;
            Qs[(r + 8) * 132 + c + 1] = o[nt][3] * inv1;
        }
    }
    __syncthreads();
    float* AOg = g_ao + ((size_t)(b * SEQ + q0)) * DMODEL + h * HD;
#pragma unroll 4
    for (int i = 0; i < 64; i++) {
        int f = tid + i * 256;
        int r = f >> 7, d = f & 127;
        AOg[(size_t)r * DMODEL + d] = Qs[r * 132 + d];
    }
}

// ---------------------------------------------------------------------------
extern "C" void kernel_launch(void* const* d_in, const int* in_sizes, int n_in,
                              void* d_out, int out_size)
{
    const float* hs   = (const float*)d_in[0];
    const float* cosp = (const float*)d_in[1];
    const float* sinp = (const float*)d_in[2];
    const float* wq   = (const float*)d_in[3];
    const float* wk   = (const float*)d_in[4];
    const float* wv   = (const float*)d_in[5];
    const float* wo   = (const float*)d_in[6];
    float* out = (float*)d_out;

    constexpr int SMEM_GEMM = 4 * 128 * 36 * 4;                                   // 73728 B
    constexpr int SMEM_ATTN = (128 * 132 + 64 * 132 + 128 * 68 + 128 * 68) * 4;   // 171008 B

    cudaFuncSetAttribute((const void*)gemm_tf32<0>,
                         cudaFuncAttributeMaxDynamicSharedMemorySize, SMEM_GEMM);
    cudaFuncSetAttribute((const void*)gemm_tf32<1>,
                         cudaFuncAttributeMaxDynamicSharedMemorySize, SMEM_GEMM);
    cudaFuncSetAttribute((const void*)attn_kernel,
                         cudaFuncAttributeMaxDynamicSharedMemorySize, SMEM_ATTN);

    // 1) fused QKV projection + RoPE (+ scale folded into Q), V stored transposed
    gemm_tf32<0><<<dim3(48, 32), 256, SMEM_GEMM>>>(hs, wq, wk, wv, cosp, sinp, nullptr);
    // 2) causal GQA flash attention
    attn_kernel<<<dim3(16, 32, 2), 256, SMEM_ATTN>>>();
    // 3) output projection
    gemm_tf32<1><<<dim3(32, 32), 256, SMEM_GEMM>>>(nullptr, wo, nullptr, nullptr,
                                                   nullptr, nullptr, out);
}